// round 14
// baseline (speedup 1.0000x reference)
#include <cuda_runtime.h>
#include <cstdint>

#define N_NODES 4096
#define FIN     512
#define HID     64
#define HEADS   8
#define FOUT    256
#define NHALF   (N_NODES / 2)

// ---------------- scratch ----------------
__device__ uint32_t g_Vb1[(size_t)HEADS * NHALF * HID];   // bf16 pairs [h][jp][d]
__device__ float    g_h[(size_t)N_NODES * (HEADS * HID)]; // fp32
__device__ uint32_t g_Vb2[(size_t)NHALF * FOUT];          // bf16 pairs [jp][d]
__device__ float    g_num[(size_t)4 * N_NODES * FOUT];    // layer2 jsplit partials
__device__ float    g_den[4 * N_NODES];
__device__ uint2    g_adjT[(size_t)64 * N_NODES];         // transposed bitmask [tile][row]
__device__ float    g_s1[HEADS * N_NODES];
__device__ float    g_s2[HEADS * N_NODES];
__device__ float    g_s1b[N_NODES];
__device__ float    g_s2b[N_NODES];
__device__ unsigned g_enc1[HEADS];
__device__ float    g_Ea1[HEADS * N_NODES], g_Eb1[HEADS * N_NODES];
__device__ uint4    g_T1[HEADS * NHALF];                  // {Fa2, Fb2, s2bf2, 0}
__device__ float    g_Ea2[N_NODES], g_Eb2[N_NODES];
__device__ uint4    g_T2[NHALF];

// ---------------- helpers ----------------
__device__ __forceinline__ uint32_t smem_u32(const void* p) {
    uint32_t a;
    asm("{ .reg .u64 t; cvta.to.shared.u64 t, %1; cvt.u32.u64 %0, t; }" : "=r"(a) : "l"(p));
    return a;
}
#define CP_ASYNC16(dst, src) \
    asm volatile("cp.async.cg.shared.global [%0], [%1], 16;" :: "r"(dst), "l"(src) : "memory")
#define CP_COMMIT() asm volatile("cp.async.commit_group;" ::: "memory")
#define CP_WAIT(n)  asm volatile("cp.async.wait_group %0;" :: "n"(n) : "memory")

__device__ __forceinline__ uint32_t packbf(float lo, float hi) {
    uint32_t r;
    asm("cvt.rn.bf16x2.f32 %0, %1, %2;" : "=r"(r) : "f"(hi), "f"(lo));
    return r;
}
__device__ __forceinline__ uint32_t bge(uint32_t a, uint32_t b) {
    uint32_t r;
    asm("set.ge.u32.bf16x2 %0, %1, %2;" : "=r"(r) : "r"(a), "r"(b));
    return r;
}
__device__ __forceinline__ uint32_t bmul2(uint32_t a, uint32_t b) {
    uint32_t r;
    asm("mul.rn.bf16x2 %0, %1, %2;" : "=r"(r) : "r"(a), "r"(b));
    return r;
}
// bits 0,1 of x -> {lo half mask, hi half mask}
__device__ __forceinline__ uint32_t amask2(uint32_t x) {
    return ((x & 1u) | ((x & 2u) << 15)) * 0xFFFFu;
}
__device__ __forceinline__ void mma_bf16(float* d, const uint32_t* a,
                                         uint32_t b0, uint32_t b1) {
    asm volatile(
        "mma.sync.aligned.m16n8k16.row.col.f32.bf16.bf16.f32 "
        "{%0,%1,%2,%3},{%4,%5,%6,%7},{%8,%9},{%0,%1,%2,%3};"
        : "+f"(d[0]), "+f"(d[1]), "+f"(d[2]), "+f"(d[3])
        : "r"(a[0]), "r"(a[1]), "r"(a[2]), "r"(a[3]), "r"(b0), "r"(b1));
}
__device__ __forceinline__ void mma_tf32(float* d, const float* a, float b0, float b1) {
    asm volatile(
        "mma.sync.aligned.m16n8k8.row.col.f32.tf32.tf32.f32 "
        "{%0,%1,%2,%3},{%4,%5,%6,%7},{%8,%9},{%0,%1,%2,%3};"
        : "+f"(d[0]), "+f"(d[1]), "+f"(d[2]), "+f"(d[3])
        : "r"(__float_as_uint(a[0])), "r"(__float_as_uint(a[1])),
          "r"(__float_as_uint(a[2])), "r"(__float_as_uint(a[3])),
          "r"(__float_as_uint(b0)),   "r"(__float_as_uint(b1)));
}
__device__ __forceinline__ unsigned encf(float f) {
    unsigned u = __float_as_uint(f);
    return (u & 0x80000000u) ? ~u : (u | 0x80000000u);
}
__device__ __forceinline__ float decf(unsigned e) {
    return __uint_as_float((e & 0x80000000u) ? (e & 0x7fffffffu) : ~e);
}
__device__ __forceinline__ float fast_exp(float x) {
    float y = x * 1.4426950408889634f;
    float t = y + 12582912.0f;
    int   i = __float_as_int(t);
    float f = y - (t - 12582912.0f);
    float p = 1.5403530e-4f;
    p = fmaf(p, f, 1.3333558e-3f);
    p = fmaf(p, f, 9.6181291e-3f);
    p = fmaf(p, f, 5.5504109e-2f);
    p = fmaf(p, f, 2.4022651e-1f);
    p = fmaf(p, f, 6.9314718e-1f);
    p = fmaf(p, f, 1.0f);
    return __int_as_float(__float_as_int(p) + (i << 23));
}
__device__ __forceinline__ float lrelu02(float t) { return fmaxf(t, 0.2f * t); }
__device__ __forceinline__ float elu1(float x) { return x > 0.f ? x : expm1f(x); }

// ---------------- pack adj -> transposed bitmask [tile][row] + zero atomics ----------------
__global__ __launch_bounds__(256) void pack_adj(const int* __restrict__ adj,
                                                uint2* __restrict__ adjT,
                                                float* s1b, float* s2b,
                                                unsigned* e1) {
    int idx = blockIdx.x * 256 + threadIdx.x;    // row*64 + tile
    int t = idx & 63, row = idx >> 6;
    const int4* src = (const int4*)(adj + (size_t)row * N_NODES + t * 64);
    uint32_t lo = 0, hi = 0;
#pragma unroll
    for (int q = 0; q < 8; q++) {
        int4 a = src[q];
        uint32_t m = (a.x > 0 ? 1u : 0u) | (a.y > 0 ? 2u : 0u)
                   | (a.z > 0 ? 4u : 0u) | (a.w > 0 ? 8u : 0u);
        lo |= m << (q * 4);
    }
#pragma unroll
    for (int q = 8; q < 16; q++) {
        int4 a = src[q];
        uint32_t m = (a.x > 0 ? 1u : 0u) | (a.y > 0 ? 2u : 0u)
                   | (a.z > 0 ? 4u : 0u) | (a.w > 0 ? 8u : 0u);
        hi |= m << ((q - 8) * 4);
    }
    adjT[(size_t)t * N_NODES + row] = make_uint2(lo, hi);
    if (blockIdx.x < 16) {
        int i = blockIdx.x * 256 + threadIdx.x;
        s1b[i] = 0.f; s2b[i] = 0.f;
    }
    if (blockIdx.x == 16 && threadIdx.x < HEADS) e1[threadIdx.x] = 0u;
}

// ---------------- layer-1 row factors + pair tables ----------------
__global__ __launch_bounds__(256) void prep1(
    const float* __restrict__ s1, const float* __restrict__ s2,
    const unsigned* __restrict__ enc, float* __restrict__ Ea,
    float* __restrict__ Eb, uint4* __restrict__ T)
{
    int i = blockIdx.x * 256 + threadIdx.x;
    int z = i >> 12;
    float m2 = decf(enc[z]);
    float v1 = s1[i];
    float M = lrelu02(v1 + m2);
    Ea[i] = fast_exp(v1 - M);
    Eb[i] = fast_exp(0.2f * v1 - M);
    if (i < HEADS * NHALF) {
        int head = i >> 11, jp = i & 2047;
        int b = head * N_NODES + 2 * jp;
        float va = s2[b], vb = s2[b + 1];
        T[i] = make_uint4(packbf(fast_exp(va), fast_exp(vb)),
                          packbf(fast_exp(0.2f * va), fast_exp(0.2f * vb)),
                          packbf(va, vb), 0u);
    }
}

// ---------------- layer-2: s2 max + row factors + pair tables (1 block) ----------------
__global__ __launch_bounds__(256) void max2_prep2(
    const float* __restrict__ s1, const float* __restrict__ s2,
    float* __restrict__ Ea, float* __restrict__ Eb, uint4* __restrict__ T)
{
    __shared__ float red[256];
    float m = -1e30f;
    for (int i = threadIdx.x; i < N_NODES; i += 256) m = fmaxf(m, s2[i]);
    red[threadIdx.x] = m;
    __syncthreads();
    for (int s = 128; s > 0; s >>= 1) {
        if (threadIdx.x < s) red[threadIdx.x] = fmaxf(red[threadIdx.x], red[threadIdx.x + s]);
        __syncthreads();
    }
    float m2 = red[0];
    for (int r = threadIdx.x; r < N_NODES; r += 256) {
        float v1 = s1[r];
        float M = lrelu02(v1 + m2);
        Ea[r] = fast_exp(v1 - M);
        Eb[r] = fast_exp(0.2f * v1 - M);
    }
    for (int jp = threadIdx.x; jp < NHALF; jp += 256) {
        float va = s2[2 * jp], vb = s2[2 * jp + 1];
        T[jp] = make_uint4(packbf(fast_exp(va), fast_exp(vb)),
                           packbf(fast_exp(0.2f * va), fast_exp(0.2f * vb)),
                           packbf(va, vb), 0u);
    }
}

// ------------- tf32 tensor GEMM, fused epilogue -------------
template<int L1>
__global__ void __launch_bounds__(256) gemm_tc(
    const float* __restrict__ A, const float* __restrict__ B,
    uint32_t* __restrict__ Vb, const float* __restrict__ a1,
    const float* __restrict__ a2, float* __restrict__ s1, float* __restrict__ s2,
    unsigned* __restrict__ enc, int NB, int bB, int bV, int bA, int bS)
{
    constexpr int SA = 20, SB = 72;
    __shared__ float Asm[2][128 * SA];
    __shared__ float Bsm[2][16 * SB];
    __shared__ float a1sm[64], a2sm[64];
    int tid = threadIdx.x, wid = tid >> 5, lane = tid & 31;
    int g = lane >> 2, c = lane & 3;
    int z = blockIdx.z, n0 = blockIdx.y * 64, i0 = blockIdx.x * 128;
    B  += (size_t)z * bB;
    Vb += (size_t)z * bV;
    a1 += (size_t)z * bA;  a2 += (size_t)z * bA;
    s1 += (size_t)z * bS;  s2 += (size_t)z * bS;
    if (tid < 64) { a1sm[tid] = a1[n0 + tid]; a2sm[tid] = a2[n0 + tid]; }
    uint32_t abase = smem_u32(Asm), bbase = smem_u32(Bsm);

    auto issue = [&](int t, int buf) {
        int k0 = t * 16;
#pragma unroll
        for (int u = 0; u < 2; u++) {
            int idx = tid + 256 * u;
            int r = idx >> 2, q = idx & 3;
            CP_ASYNC16(abase + (uint32_t)(buf * 128 * SA + r * SA + q * 4) * 4,
                       A + (size_t)(i0 + r) * FIN + k0 + q * 4);
        }
        {
            int r = tid >> 4, q = tid & 15;
            CP_ASYNC16(bbase + (uint32_t)(buf * 16 * SB + r * SB + q * 4) * 4,
                       B + (size_t)(k0 + r) * NB + n0 + q * 4);
        }
        CP_COMMIT();
    };

    float acc[8][4] = {};
    issue(0, 0);
    for (int t = 0; t < 32; t++) {
        if (t + 1 < 32) { issue(t + 1, (t + 1) & 1); CP_WAIT(1); }
        else            { CP_WAIT(0); }
        __syncthreads();
        const float* As = &Asm[t & 1][0];
        const float* Bs = &Bsm[t & 1][0];
#pragma unroll
        for (int ks = 0; ks < 2; ks++) {
            int k8 = ks * 8;
            float af[4];
            af[0] = As[(16 * wid + g) * SA + k8 + c];
            af[1] = As[(16 * wid + 8 + g) * SA + k8 + c];
            af[2] = As[(16 * wid + g) * SA + k8 + c + 4];
            af[3] = As[(16 * wid + 8 + g) * SA + k8 + c + 4];
#pragma unroll
            for (int f = 0; f < 8; f++) {
                float b0 = Bs[(k8 + c) * SB + 8 * f + g];
                float b1 = Bs[(k8 + c + 4) * SB + 8 * f + g];
                mma_tf32(acc[f], af, b0, b1);
            }
        }
        __syncthreads();
    }

    // ---- epilogue: bf16 row-pair V via shfl pairing ----
    int rA = i0 + 16 * wid + g, rB = rA + 8;
#pragma unroll
    for (int f = 0; f < 8; f++) {
        float p0 = __shfl_xor_sync(~0u, acc[f][0], 4);
        float p1 = __shfl_xor_sync(~0u, acc[f][1], 4);
        float p2 = __shfl_xor_sync(~0u, acc[f][2], 4);
        float p3 = __shfl_xor_sync(~0u, acc[f][3], 4);
        if (!(g & 1)) {
            int col = n0 + 8 * f + 2 * c;
            uint2 v0; v0.x = packbf(acc[f][0], p0); v0.y = packbf(acc[f][1], p1);
            *(uint2*)&Vb[(size_t)(rA >> 1) * NB + col] = v0;
            uint2 v1; v1.x = packbf(acc[f][2], p2); v1.y = packbf(acc[f][3], p3);
            *(uint2*)&Vb[(size_t)(rB >> 1) * NB + col] = v1;
        }
    }
    // ---- epilogue: s1/s2 (exact fp32 from accumulators) ----
    float u1 = 0.f, u2 = 0.f, w1 = 0.f, w2 = 0.f;
#pragma unroll
    for (int f = 0; f < 8; f++) {
        int col = 8 * f + 2 * c;
        u1 += acc[f][0] * a1sm[col] + acc[f][1] * a1sm[col + 1];
        u2 += acc[f][0] * a2sm[col] + acc[f][1] * a2sm[col + 1];
        w1 += acc[f][2] * a1sm[col] + acc[f][3] * a1sm[col + 1];
        w2 += acc[f][2] * a2sm[col] + acc[f][3] * a2sm[col + 1];
    }
    u1 += __shfl_xor_sync(~0u, u1, 1); u1 += __shfl_xor_sync(~0u, u1, 2);
    u2 += __shfl_xor_sync(~0u, u2, 1); u2 += __shfl_xor_sync(~0u, u2, 2);
    w1 += __shfl_xor_sync(~0u, w1, 1); w1 += __shfl_xor_sync(~0u, w1, 2);
    w2 += __shfl_xor_sync(~0u, w2, 1); w2 += __shfl_xor_sync(~0u, w2, 2);
    if (c == 0) {
        if (L1) {
            s1[rA] = u1; s2[rA] = u2; s1[rB] = w1; s2[rB] = w2;
            atomicMax(&enc[z], encf(u2));
            atomicMax(&enc[z], encf(w2));
        } else {
            atomicAdd(&s1[rA], u1); atomicAdd(&s2[rA], u2);
            atomicAdd(&s1[rB], w1); atomicAdd(&s2[rB], w2);
        }
    }
}

// ==== fused attention: bf16x2 table P, staged inputs, mma denominator, col-split ====
// 8 warps = ROWG row-groups x COLGRPS col-groups (CW cols each).
// MODE 0 (layer1): blockIdx.z = head; div+elu in-kernel -> hbuf cols head*64.
// MODE 1 (layer2): blockIdx.z = jsplit; partial num/den; cols blockIdx.y*NCOLS+colofs.
template<int NCOLS, int RPB, int TT, int MODE>
__global__ void __launch_bounds__(256) attn_mma(
    const uint32_t* __restrict__ Vb, int vrstride, int vzstride,
    const float* __restrict__ s1g, const float* __restrict__ Eag,
    const float* __restrict__ Ebg, const uint4* __restrict__ Tg,
    const uint2* __restrict__ adjT,
    float* __restrict__ outp, float* __restrict__ denp)
{
    constexpr int SVP = NCOLS + 8;
    constexpr int ROWG = RPB / 16;
    constexpr int COLGRPS = 8 / ROWG;
    constexpr int CW = NCOLS / COLGRPS;
    constexpr int NFRAG = CW / 8;
    constexpr int ADJ_OFF = 32 * SVP;          // u32 units
    constexpr int T_OFF   = ADJ_OFF + RPB * 2;
    constexpr int BUF_U32 = T_OFF + 128;       // T: 32 x uint4
    extern __shared__ uint32_t vsm[];

    int tid = threadIdx.x, wid = tid >> 5, lane = tid & 31;
    int g = lane >> 2, c = lane & 3;
    int z = blockIdx.z;
    int head = (MODE == 0) ? z : 0;
    const float* s1p = s1g + head * N_NODES;
    const float* Eap = Eag + head * N_NODES;
    const float* Ebp = Ebg + head * N_NODES;
    const uint4* Tp = Tg + head * NHALF;
    const uint32_t* vsrc = Vb + ((MODE == 0) ? (size_t)head * vzstride
                                             : (size_t)blockIdx.y * NCOLS);
    int jbase = (MODE == 1) ? z * (TT * 64) : 0;
    int tbase = jbase >> 6;
    int prbase = jbase >> 1;

    int i0 = blockIdx.x * RPB;
    int rowgrp = wid % ROWG, colgrp = wid / ROWG;
    int colofs = colgrp * CW;
    int rloc = rowgrp * 16 + g;
    int r0 = i0 + rloc;

    float s1a = s1p[r0], s1b_ = s1p[r0 + 8];
    uint32_t thA2 = packbf(-s1a, -s1a), thB2 = packbf(-s1b_, -s1b_);
    uint32_t EaA2 = packbf(Eap[r0], Eap[r0]);
    uint32_t EbA2 = packbf(Ebp[r0], Ebp[r0]);
    uint32_t EaB2 = packbf(Eap[r0 + 8], Eap[r0 + 8]);
    uint32_t EbB2 = packbf(Ebp[r0 + 8], Ebp[r0 + 8]);

    float acc[NFRAG][4];
#pragma unroll
    for (int f = 0; f < NFRAG; f++)
#pragma unroll
        for (int q = 0; q < 4; q++) acc[f][q] = 0.f;
    float accd[4] = {0.f, 0.f, 0.f, 0.f};
    uint32_t aPn[4][4];
    uint32_t vbase = smem_u32(vsm);
    uint32_t bden = (g == 0) ? 0x3F803F80u : 0u;   // bf16 {1,1} on n==0

    auto issueV = [&](int tl) {
        int buf = tl % 3;
        uint32_t bb = vbase + (uint32_t)(buf * BUF_U32) * 4;
        int pr0 = prbase + tl * 32;
        int tabs = tbase + tl;
#pragma unroll
        for (int u = 0; u < (32 * NCOLS / 4) / 256; u++) {
            int idx = tid + 256 * u;
            int jp = idx / (NCOLS / 4);
            int q  = idx % (NCOLS / 4);
            CP_ASYNC16(bb + (uint32_t)(jp * SVP + q * 4) * 4,
                       vsrc + (size_t)(pr0 + jp) * vrstride + q * 4);
        }
        if (tid < RPB / 2) {
            CP_ASYNC16(bb + (uint32_t)ADJ_OFF * 4 + tid * 16,
                       adjT + (size_t)tabs * N_NODES + i0 + 2 * tid);
        } else if (tid < RPB / 2 + 32) {
            int q = tid - RPB / 2;
            CP_ASYNC16(bb + (uint32_t)T_OFF * 4 + q * 16, Tp + pr0 + q);
        }
    };

    auto computeP = [&](int tl) {
        int buf = tl % 3;
        const uint32_t* bb = vsm + buf * BUF_U32;
        const uint2* adjsm = (const uint2*)(bb + ADJ_OFF);
        const uint4* Tsm = (const uint4*)(bb + T_OFF);
        uint2 w0 = adjsm[rloc];
        uint2 w1 = adjsm[rloc + 8];
        unsigned long long bm0 = (unsigned long long)w0.x | ((unsigned long long)w0.y << 32);
        unsigned long long bm1 = (unsigned long long)w1.x | ((unsigned long long)w1.y << 32);
        uint32_t l0 = (uint32_t)(bm0 >> (2 * c)), h0 = ((uint32_t)(bm0 >> 32)) >> (2 * c);
        uint32_t l1 = (uint32_t)(bm1 >> (2 * c)), h1 = ((uint32_t)(bm1 >> 32)) >> (2 * c);
#pragma unroll
        for (int ks = 0; ks < 4; ks++) {
            uint32_t wA = (ks < 2) ? l0 : h0;
            uint32_t wB = (ks < 2) ? l1 : h1;
            const int sh = (ks & 1) * 16;
            int jp0 = 8 * ks + c, jp1 = jp0 + 4;
            uint4 t0 = Tsm[jp0];
            uint4 t1 = Tsm[jp1];
            uint32_t xA = wA >> sh, xB = wB >> sh;
            uint32_t aA0 = amask2(xA),      aB0 = amask2(xB);
            uint32_t aA1 = amask2(xA >> 8), aB1 = amask2(xB >> 8);
            uint32_t mA0 = bge(t0.z, thA2), mB0 = bge(t0.z, thB2);
            uint32_t mA1 = bge(t1.z, thA2), mB1 = bge(t1.z, thB2);
            uint32_t FaA0 = bmul2(EaA2, t0.x), FbA0 = bmul2(EbA2, t0.y);
            uint32_t FaB0 = bmul2(EaB2, t0.x), FbB0 = bmul2(EbB2, t0.y);
            uint32_t FaA1 = bmul2(EaA2, t1.x), FbA1 = bmul2(EbA2, t1.y);
            uint32_t FaB1 = bmul2(EaB2, t1.x), FbB1 = bmul2(EbB2, t1.y);
            aPn[ks][0] = ((FaA0 & mA0) | (FbA0 & ~mA0)) & aA0;
            aPn[ks][1] = ((FaB0 & mB0) | (FbB0 & ~mB0)) & aB0;
            aPn[ks][2] = ((FaA1 & mA1) | (FbA1 & ~mA1)) & aA1;
            aPn[ks][3] = ((FaB1 & mB1) | (FbB1 & ~mB1)) & aB1;
        }
    };

    issueV(0); CP_COMMIT();
    issueV(1); CP_COMMIT();
    CP_WAIT(1);
    __syncthreads();
    computeP(0);

    for (int t = 0; t < TT; t++) {
        if (t + 2 < TT) { issueV(t + 2); CP_COMMIT(); }
        const uint32_t* vb = vsm + (t % 3) * BUF_U32;
#pragma unroll
        for (int f = 0; f < NFRAG; f++) {
            int col = colofs + 8 * f + g;
#pragma unroll
            for (int ks = 0; ks < 4; ks++) {
                uint32_t b0 = vb[(ks * 8 + c) * SVP + col];
                uint32_t b1 = vb[(ks * 8 + c + 4) * SVP + col];
                mma_bf16(acc[f], aPn[ks], b0, b1);
            }
        }
        if (colgrp == 0) {
            mma_bf16(accd, aPn[0], bden, bden);
            mma_bf16(accd, aPn[1], bden, bden);
            mma_bf16(accd, aPn[2], bden, bden);
            mma_bf16(accd, aPn[3], bden, bden);
        }
        if (t + 1 < TT) {
            if (t + 2 < TT) CP_WAIT(1); else CP_WAIT(0);
            __syncthreads();
            computeP(t + 1);
        }
    }

    if (MODE == 0) {
        // broadcast denominators to all col-groups via smem
        float* densm = (float*)vsm;
        __syncthreads();
        if (colgrp == 0 && c == 0) {
            densm[rloc] = accd[0];
            densm[rloc + 8] = accd[2];
        }
        __syncthreads();
        float dinv0 = 1.0f / densm[rloc];
        float dinv1 = 1.0f / densm[rloc + 8];
        float* row0 = outp + (size_t)r0 * (HEADS * HID) + head * 64 + colofs;
        float* row1 = row0 + 8 * (HEADS * HID);
#pragma unroll
        for (int f = 0; f < NFRAG; f++) {
            int col = 8 * f + 2 * c;
            float2 v0, v1;
            v0.x = elu1(acc[f][0] * dinv0); v0.y = elu1(acc[f][1] * dinv0);
            v1.x = elu1(acc[f][2] * dinv1); v1.y = elu1(acc[f][3] * dinv1);
            *(float2*)&row0[col] = v0;
            *(float2*)&row1[col] = v1;
        }
    } else {
        float* num = outp + (size_t)z * (N_NODES * FOUT);
        int outc = blockIdx.y * NCOLS + colofs;
        float* row0 = num + (size_t)r0 * FOUT + outc;
        float* row1 = row0 + 8 * FOUT;
#pragma unroll
        for (int f = 0; f < NFRAG; f++) {
            int col = 8 * f + 2 * c;
            float2 v0, v1;
            v0.x = acc[f][0]; v0.y = acc[f][1];
            v1.x = acc[f][2]; v1.y = acc[f][3];
            *(float2*)&row0[col] = v0;
            *(float2*)&row1[col] = v1;
        }
        if (c == 0 && colgrp == 0 && blockIdx.y == 0) {
            denp[z * N_NODES + r0] = accd[0];
            denp[z * N_NODES + r0 + 8] = accd[2];
        }
    }
}

// ---------------- combine 4 partials + elu + log_softmax ----------------
__global__ __launch_bounds__(256) void final_kernel(
    const float* __restrict__ num, const float* __restrict__ den,
    float* __restrict__ out)
{
    int warp = threadIdx.x >> 5, lane = threadIdx.x & 31;
    int row = blockIdx.x * 8 + warp;
    const float* n0 = num + (size_t)row * FOUT;
    float d = den[row] + den[N_NODES + row] + den[2 * N_NODES + row] + den[3 * N_NODES + row];
    float dinv = 1.0f / d;
    float v[8];
    float mx = -1e30f;
#pragma unroll
    for (int k = 0; k < 8; k++) {
        int idx = lane + k * 32;
        float x = n0[idx] + n0[idx + (size_t)N_NODES * FOUT]
                + n0[idx + (size_t)2 * N_NODES * FOUT]
                + n0[idx + (size_t)3 * N_NODES * FOUT];
        x = elu1(x * dinv);
        v[k] = x;
        mx = fmaxf(mx, x);
    }
#pragma unroll
    for (int o = 16; o > 0; o >>= 1) mx = fmaxf(mx, __shfl_xor_sync(~0u, mx, o));
    float s = 0.f;
#pragma unroll
    for (int k = 0; k < 8; k++) s += fast_exp(v[k] - mx);
#pragma unroll
    for (int o = 16; o > 0; o >>= 1) s += __shfl_xor_sync(~0u, s, o);
    float lse = mx + logf(s);
#pragma unroll
    for (int k = 0; k < 8; k++) out[(size_t)row * FOUT + lane + k * 32] = v[k] - lse;
}

// ---------------- launcher ----------------
extern "C" void kernel_launch(void* const* d_in, const int* in_sizes, int n_in,
                              void* d_out, int out_size)
{
    const float* x        = (const float*)d_in[0];
    const int*   adj      = (const int*)  d_in[1];
    const float* W_heads  = (const float*)d_in[2];
    const float* a1_heads = (const float*)d_in[3];
    const float* a2_heads = (const float*)d_in[4];
    const float* W_out    = (const float*)d_in[5];
    const float* a1_out   = (const float*)d_in[6];
    const float* a2_out   = (const float*)d_in[7];
    float* out = (float*)d_out;

    float *hbuf, *num, *den, *s1, *s2, *s1b, *s2b, *Ea1, *Eb1, *Ea2, *Eb2;
    uint32_t *Vb1, *Vb2;
    uint4 *T1, *T2;
    uint2 *adjT;
    unsigned *enc1;
    cudaGetSymbolAddress((void**)&Vb1,  g_Vb1);
    cudaGetSymbolAddress((void**)&hbuf, g_h);
    cudaGetSymbolAddress((void**)&Vb2,  g_Vb2);
    cudaGetSymbolAddress((void**)&num,  g_num);
    cudaGetSymbolAddress((void**)&den,  g_den);
    cudaGetSymbolAddress((void**)&adjT, g_adjT);
    cudaGetSymbolAddress((void**)&s1,   g_s1);
    cudaGetSymbolAddress((void**)&s2,   g_s2);
    cudaGetSymbolAddress((void**)&s1b,  g_s1b);
    cudaGetSymbolAddress((void**)&s2b,  g_s2b);
    cudaGetSymbolAddress((void**)&enc1, g_enc1);
    cudaGetSymbolAddress((void**)&Ea1,  g_Ea1);
    cudaGetSymbolAddress((void**)&Eb1,  g_Eb1);
    cudaGetSymbolAddress((void**)&T1,   g_T1);
    cudaGetSymbolAddress((void**)&Ea2,  g_Ea2);
    cudaGetSymbolAddress((void**)&Eb2,  g_Eb2);
    cudaGetSymbolAddress((void**)&T2,   g_T2);

    const int SM1 = (32 * 72 + 128 + 128) * 4 * 3;    // 30720 B (RPB=64)
    const int SM2 = (32 * 136 + 128 + 128) * 4 * 3;   // 55296 B
    cudaFuncSetAttribute(attn_mma<HID, 64, 64, 0>,
                         cudaFuncAttributeMaxDynamicSharedMemorySize, SM1);
    cudaFuncSetAttribute(attn_mma<128, 64, 16, 1>,
                         cudaFuncAttributeMaxDynamicSharedMemorySize, SM2);

    // 0: adj transposed bitmask + zeroing
    pack_adj<<<(N_NODES * 64) / 256, 256>>>(adj, adjT, s1b, s2b, enc1);
    // 1: layer-1 GEMM (+V row-pair bf16, s1/s2, s2max)
    gemm_tc<1><<<dim3(N_NODES / 128, 1, HEADS), 256>>>(
        x, W_heads, Vb1, a1_heads, a2_heads, s1, s2, enc1,
        HID, FIN * HID, NHALF * HID, HID, N_NODES);
    // 2: layer-1 row factors + pair tables
    prep1<<<(HEADS * N_NODES) / 256, 256>>>(s1, s2, enc1, Ea1, Eb1, T1);
    // 3: layer-1 attention, col-split, grid 512 (<- profiled slot)
    attn_mma<HID, 64, 64, 0><<<dim3(N_NODES / 64, 1, HEADS), 256, SM1>>>(
        Vb1, HID, NHALF * HID, s1, Ea1, Eb1, T1, adjT, hbuf, nullptr);
    // 4: layer-2 GEMM
    gemm_tc<0><<<dim3(N_NODES / 128, FOUT / 64, 1), 256>>>(
        hbuf, W_out, Vb2, a1_out, a2_out, s1b, s2b, enc1, FOUT, 0, 0, 0, 0);
    // 5: layer-2 max + tables
    max2_prep2<<<1, 256>>>(s1b, s2b, Ea2, Eb2, T2);
    // 6: layer-2 attention, j-split x4, grid 512
    attn_mma<128, 64, 16, 1><<<dim3(N_NODES / 64, 2, 4), 256, SM2>>>(
        Vb2, FOUT, 0, s1b, Ea2, Eb2, T2, adjT, num, den);
    // 7: combine 4 partials + elu + log_softmax
    final_kernel<<<N_NODES / 8, 256>>>(num, den, out);
}

// round 15
// speedup vs baseline: 1.2411x; 1.2411x over previous
#include <cuda_runtime.h>
#include <cstdint>

#define N_NODES 4096
#define FIN     512
#define HID     64
#define HEADS   8
#define FOUT    256
#define NHALF   (N_NODES / 2)

// ---------------- scratch ----------------
__device__ uint32_t g_Vb1[(size_t)HEADS * HID * NHALF];   // bf16 pairs, d-major [h][d][jp]
__device__ float    g_h[(size_t)N_NODES * (HEADS * HID)]; // fp32
__device__ uint32_t g_Vb2[(size_t)FOUT * NHALF];          // bf16 pairs, d-major [d][jp]
__device__ float    g_num[(size_t)2 * N_NODES * FOUT];    // layer2 jsplit partials
__device__ float    g_den[2 * N_NODES];
__device__ uint2    g_adjT[(size_t)64 * N_NODES];         // transposed bitmask [tile][row]
__device__ float    g_s1[HEADS * N_NODES];
__device__ float    g_s2[HEADS * N_NODES];
__device__ float    g_s1b[N_NODES];
__device__ float    g_s2b[N_NODES];
__device__ unsigned g_enc1[HEADS];
__device__ float    g_Ea1[HEADS * N_NODES], g_Eb1[HEADS * N_NODES];
__device__ uint4    g_T1[HEADS * NHALF];                  // {Fa2, Fb2, s2bf2, 0}
__device__ float    g_Ea2[N_NODES], g_Eb2[N_NODES];
__device__ uint4    g_T2[NHALF];

// ---------------- helpers ----------------
__device__ __forceinline__ uint32_t smem_u32(const void* p) {
    uint32_t a;
    asm("{ .reg .u64 t; cvta.to.shared.u64 t, %1; cvt.u32.u64 %0, t; }" : "=r"(a) : "l"(p));
    return a;
}
#define CP_ASYNC16(dst, src) \
    asm volatile("cp.async.cg.shared.global [%0], [%1], 16;" :: "r"(dst), "l"(src) : "memory")
#define CP_COMMIT() asm volatile("cp.async.commit_group;" ::: "memory")
#define CP_WAIT(n)  asm volatile("cp.async.wait_group %0;" :: "n"(n) : "memory")
#define LDMX4(r0, r1, r2, r3, addr) \
    asm volatile("ldmatrix.sync.aligned.m8n8.x4.shared.b16 {%0,%1,%2,%3}, [%4];" \
        : "=r"(r0), "=r"(r1), "=r"(r2), "=r"(r3) : "r"(addr))

__device__ __forceinline__ uint32_t packbf(float lo, float hi) {
    uint32_t r;
    asm("cvt.rn.bf16x2.f32 %0, %1, %2;" : "=r"(r) : "f"(hi), "f"(lo));
    return r;
}
__device__ __forceinline__ uint32_t bge(uint32_t a, uint32_t b) {
    uint32_t r;
    asm("set.ge.u32.bf16x2 %0, %1, %2;" : "=r"(r) : "r"(a), "r"(b));
    return r;
}
__device__ __forceinline__ uint32_t bmul2(uint32_t a, uint32_t b) {
    uint32_t r;
    asm("mul.rn.bf16x2 %0, %1, %2;" : "=r"(r) : "r"(a), "r"(b));
    return r;
}
// bits 0,1 of x -> {lo half mask, hi half mask}
__device__ __forceinline__ uint32_t amask2(uint32_t x) {
    return ((x & 1u) | ((x & 2u) << 15)) * 0xFFFFu;
}
__device__ __forceinline__ void mma_bf16(float* d, const uint32_t* a,
                                         uint32_t b0, uint32_t b1) {
    asm volatile(
        "mma.sync.aligned.m16n8k16.row.col.f32.bf16.bf16.f32 "
        "{%0,%1,%2,%3},{%4,%5,%6,%7},{%8,%9},{%0,%1,%2,%3};"
        : "+f"(d[0]), "+f"(d[1]), "+f"(d[2]), "+f"(d[3])
        : "r"(a[0]), "r"(a[1]), "r"(a[2]), "r"(a[3]), "r"(b0), "r"(b1));
}
__device__ __forceinline__ void mma_tf32(float* d, const float* a, float b0, float b1) {
    asm volatile(
        "mma.sync.aligned.m16n8k8.row.col.f32.tf32.tf32.f32 "
        "{%0,%1,%2,%3},{%4,%5,%6,%7},{%8,%9},{%0,%1,%2,%3};"
        : "+f"(d[0]), "+f"(d[1]), "+f"(d[2]), "+f"(d[3])
        : "r"(__float_as_uint(a[0])), "r"(__float_as_uint(a[1])),
          "r"(__float_as_uint(a[2])), "r"(__float_as_uint(a[3])),
          "r"(__float_as_uint(b0)),   "r"(__float_as_uint(b1)));
}
__device__ __forceinline__ unsigned encf(float f) {
    unsigned u = __float_as_uint(f);
    return (u & 0x80000000u) ? ~u : (u | 0x80000000u);
}
__device__ __forceinline__ float decf(unsigned e) {
    return __uint_as_float((e & 0x80000000u) ? (e & 0x7fffffffu) : ~e);
}
__device__ __forceinline__ float fast_exp(float x) {
    float y = x * 1.4426950408889634f;
    float t = y + 12582912.0f;
    int   i = __float_as_int(t);
    float f = y - (t - 12582912.0f);
    float p = 1.5403530e-4f;
    p = fmaf(p, f, 1.3333558e-3f);
    p = fmaf(p, f, 9.6181291e-3f);
    p = fmaf(p, f, 5.5504109e-2f);
    p = fmaf(p, f, 2.4022651e-1f);
    p = fmaf(p, f, 6.9314718e-1f);
    p = fmaf(p, f, 1.0f);
    return __int_as_float(__float_as_int(p) + (i << 23));
}
__device__ __forceinline__ float lrelu02(float t) { return fmaxf(t, 0.2f * t); }
__device__ __forceinline__ float elu1(float x) { return x > 0.f ? x : expm1f(x); }

// ---------------- pack adj -> transposed bitmask [tile][row] + zero atomics ----------------
__global__ __launch_bounds__(256) void pack_adj(const int* __restrict__ adj,
                                                uint2* __restrict__ adjT,
                                                float* s1b, float* s2b,
                                                unsigned* e1) {
    int idx = blockIdx.x * 256 + threadIdx.x;    // row*64 + tile
    int t = idx & 63, row = idx >> 6;
    const int4* src = (const int4*)(adj + (size_t)row * N_NODES + t * 64);
    uint32_t lo = 0, hi = 0;
#pragma unroll
    for (int q = 0; q < 8; q++) {
        int4 a = src[q];
        uint32_t m = (a.x > 0 ? 1u : 0u) | (a.y > 0 ? 2u : 0u)
                   | (a.z > 0 ? 4u : 0u) | (a.w > 0 ? 8u : 0u);
        lo |= m << (q * 4);
    }
#pragma unroll
    for (int q = 8; q < 16; q++) {
        int4 a = src[q];
        uint32_t m = (a.x > 0 ? 1u : 0u) | (a.y > 0 ? 2u : 0u)
                   | (a.z > 0 ? 4u : 0u) | (a.w > 0 ? 8u : 0u);
        hi |= m << ((q - 8) * 4);
    }
    adjT[(size_t)t * N_NODES + row] = make_uint2(lo, hi);
    if (blockIdx.x < 16) {
        int i = blockIdx.x * 256 + threadIdx.x;
        s1b[i] = 0.f; s2b[i] = 0.f;
    }
    if (blockIdx.x == 16 && threadIdx.x < HEADS) e1[threadIdx.x] = 0u;
}

// ---------------- layer-1 row factors + pair tables ----------------
__global__ __launch_bounds__(256) void prep1(
    const float* __restrict__ s1, const float* __restrict__ s2,
    const unsigned* __restrict__ enc, float* __restrict__ Ea,
    float* __restrict__ Eb, uint4* __restrict__ T)
{
    int i = blockIdx.x * 256 + threadIdx.x;
    int z = i >> 12;
    float m2 = decf(enc[z]);
    float v1 = s1[i];
    float M = lrelu02(v1 + m2);
    Ea[i] = fast_exp(v1 - M);
    Eb[i] = fast_exp(0.2f * v1 - M);
    if (i < HEADS * NHALF) {
        int head = i >> 11, jp = i & 2047;
        int b = head * N_NODES + 2 * jp;
        float va = s2[b], vb = s2[b + 1];
        T[i] = make_uint4(packbf(fast_exp(va), fast_exp(vb)),
                          packbf(fast_exp(0.2f * va), fast_exp(0.2f * vb)),
                          packbf(va, vb), 0u);
    }
}

// ---------------- layer-2: s2 max + row factors + pair tables (1 block) ----------------
__global__ __launch_bounds__(256) void max2_prep2(
    const float* __restrict__ s1, const float* __restrict__ s2,
    float* __restrict__ Ea, float* __restrict__ Eb, uint4* __restrict__ T)
{
    __shared__ float red[256];
    float m = -1e30f;
    for (int i = threadIdx.x; i < N_NODES; i += 256) m = fmaxf(m, s2[i]);
    red[threadIdx.x] = m;
    __syncthreads();
    for (int s = 128; s > 0; s >>= 1) {
        if (threadIdx.x < s) red[threadIdx.x] = fmaxf(red[threadIdx.x], red[threadIdx.x + s]);
        __syncthreads();
    }
    float m2 = red[0];
    for (int r = threadIdx.x; r < N_NODES; r += 256) {
        float v1 = s1[r];
        float M = lrelu02(v1 + m2);
        Ea[r] = fast_exp(v1 - M);
        Eb[r] = fast_exp(0.2f * v1 - M);
    }
    for (int jp = threadIdx.x; jp < NHALF; jp += 256) {
        float va = s2[2 * jp], vb = s2[2 * jp + 1];
        T[jp] = make_uint4(packbf(fast_exp(va), fast_exp(vb)),
                           packbf(fast_exp(0.2f * va), fast_exp(0.2f * vb)),
                           packbf(va, vb), 0u);
    }
}

// ------------- tf32 tensor GEMM, fused epilogue (d-major bf16 V, r9-verified) -------------
template<int L1>
__global__ void __launch_bounds__(256) gemm_tc(
    const float* __restrict__ A, const float* __restrict__ B,
    uint32_t* __restrict__ Vb, const float* __restrict__ a1,
    const float* __restrict__ a2, float* __restrict__ s1, float* __restrict__ s2,
    unsigned* __restrict__ enc, int NB, int bB, int bV, int bA, int bS)
{
    constexpr int SA = 20, SB = 72;
    __shared__ float Asm[2][128 * SA];
    __shared__ float Bsm[2][16 * SB];
    __shared__ float a1sm[64], a2sm[64];
    int tid = threadIdx.x, wid = tid >> 5, lane = tid & 31;
    int g = lane >> 2, c = lane & 3;
    int z = blockIdx.z, n0 = blockIdx.y * 64, i0 = blockIdx.x * 128;
    B  += (size_t)z * bB;
    Vb += (size_t)z * bV;
    a1 += (size_t)z * bA;  a2 += (size_t)z * bA;
    s1 += (size_t)z * bS;  s2 += (size_t)z * bS;
    if (tid < 64) { a1sm[tid] = a1[n0 + tid]; a2sm[tid] = a2[n0 + tid]; }
    uint32_t abase = smem_u32(Asm), bbase = smem_u32(Bsm);

    auto issue = [&](int t, int buf) {
        int k0 = t * 16;
#pragma unroll
        for (int u = 0; u < 2; u++) {
            int idx = tid + 256 * u;
            int r = idx >> 2, q = idx & 3;
            CP_ASYNC16(abase + (uint32_t)(buf * 128 * SA + r * SA + q * 4) * 4,
                       A + (size_t)(i0 + r) * FIN + k0 + q * 4);
        }
        {
            int r = tid >> 4, q = tid & 15;
            CP_ASYNC16(bbase + (uint32_t)(buf * 16 * SB + r * SB + q * 4) * 4,
                       B + (size_t)(k0 + r) * NB + n0 + q * 4);
        }
        CP_COMMIT();
    };

    float acc[8][4] = {};
    issue(0, 0);
    for (int t = 0; t < 32; t++) {
        if (t + 1 < 32) { issue(t + 1, (t + 1) & 1); CP_WAIT(1); }
        else            { CP_WAIT(0); }
        __syncthreads();
        const float* As = &Asm[t & 1][0];
        const float* Bs = &Bsm[t & 1][0];
#pragma unroll
        for (int ks = 0; ks < 2; ks++) {
            int k8 = ks * 8;
            float af[4];
            af[0] = As[(16 * wid + g) * SA + k8 + c];
            af[1] = As[(16 * wid + 8 + g) * SA + k8 + c];
            af[2] = As[(16 * wid + g) * SA + k8 + c + 4];
            af[3] = As[(16 * wid + 8 + g) * SA + k8 + c + 4];
#pragma unroll
            for (int f = 0; f < 8; f++) {
                float b0 = Bs[(k8 + c) * SB + 8 * f + g];
                float b1 = Bs[(k8 + c + 4) * SB + 8 * f + g];
                mma_tf32(acc[f], af, b0, b1);
            }
        }
        __syncthreads();
    }

    // ---- epilogue: transpose bf16 row-pairs to d-major via smem ----
    __syncthreads();
    uint32_t* ts = reinterpret_cast<uint32_t*>(&Asm[0][0]);  // [64 cols][68]
#pragma unroll
    for (int f = 0; f < 8; f++) {
        float p0 = __shfl_xor_sync(~0u, acc[f][0], 4);
        float p1 = __shfl_xor_sync(~0u, acc[f][1], 4);
        float p2 = __shfl_xor_sync(~0u, acc[f][2], 4);
        float p3 = __shfl_xor_sync(~0u, acc[f][3], 4);
        if (!(g & 1)) {
            int col = 8 * f + 2 * c;
            int jpA = 8 * wid + (g >> 1);      // local pair-row 0..63
            ts[col * 68 + jpA]           = packbf(acc[f][0], p0);
            ts[(col + 1) * 68 + jpA]     = packbf(acc[f][1], p1);
            ts[col * 68 + jpA + 4]       = packbf(acc[f][2], p2);
            ts[(col + 1) * 68 + jpA + 4] = packbf(acc[f][3], p3);
        }
    }
    __syncthreads();
    {
        int colw = tid >> 2, part = tid & 3;
        const uint4* srcv = (const uint4*)(ts + colw * 68 + part * 16);
        uint4* dstv = (uint4*)(Vb + (size_t)(n0 + colw) * NHALF + (i0 >> 1) + part * 16);
        dstv[0] = srcv[0]; dstv[1] = srcv[1]; dstv[2] = srcv[2]; dstv[3] = srcv[3];
    }

    // ---- epilogue: s1/s2 (exact fp32 from accumulators) ----
    int rA = i0 + 16 * wid + g, rB = rA + 8;
    float u1 = 0.f, u2 = 0.f, w1 = 0.f, w2 = 0.f;
#pragma unroll
    for (int f = 0; f < 8; f++) {
        int col = 8 * f + 2 * c;
        u1 += acc[f][0] * a1sm[col] + acc[f][1] * a1sm[col + 1];
        u2 += acc[f][0] * a2sm[col] + acc[f][1] * a2sm[col + 1];
        w1 += acc[f][2] * a1sm[col] + acc[f][3] * a1sm[col + 1];
        w2 += acc[f][2] * a2sm[col] + acc[f][3] * a2sm[col + 1];
    }
    u1 += __shfl_xor_sync(~0u, u1, 1); u1 += __shfl_xor_sync(~0u, u1, 2);
    u2 += __shfl_xor_sync(~0u, u2, 1); u2 += __shfl_xor_sync(~0u, u2, 2);
    w1 += __shfl_xor_sync(~0u, w1, 1); w1 += __shfl_xor_sync(~0u, w1, 2);
    w2 += __shfl_xor_sync(~0u, w2, 1); w2 += __shfl_xor_sync(~0u, w2, 2);
    if (c == 0) {
        if (L1) {
            s1[rA] = u1; s2[rA] = u2; s1[rB] = w1; s2[rB] = w2;
            atomicMax(&enc[z], encf(u2));
            atomicMax(&enc[z], encf(w2));
        } else {
            atomicAdd(&s1[rA], u1); atomicAdd(&s2[rA], u2);
            atomicAdd(&s1[rB], w1); atomicAdd(&s2[rB], w2);
        }
    }
}

// ==== fused attention: bf16x2 table P, staged inputs, ldmatrix B, mma denominator ====
// V d-major [col][jp] in smem, stride SVR=36 u32.
// MODE 0 (layer1): blockIdx.z = head; div+elu in-kernel -> hbuf cols head*64.
// MODE 1 (layer2): blockIdx.z = jsplit(2); partial num/den; cols blockIdx.y*NCOLS+colofs.
template<int NCOLS, int RPB, int TT, int MODE>
__global__ void __launch_bounds__(256) attn_mma(
    const uint32_t* __restrict__ Vb, int vzstride,
    const float* __restrict__ s1g, const float* __restrict__ Eag,
    const float* __restrict__ Ebg, const uint4* __restrict__ Tg,
    const uint2* __restrict__ adjT,
    float* __restrict__ outp, float* __restrict__ denp)
{
    constexpr int SVR = 36;                    // u32 row stride
    constexpr int ROWG = RPB / 16;
    constexpr int ADJ_OFF = NCOLS * SVR;       // u32 units
    constexpr int T_OFF   = ADJ_OFF + RPB * 2;
    constexpr int BUF_U32 = T_OFF + 128;       // T: 32 x uint4
    extern __shared__ uint32_t vsm[];

    int tid = threadIdx.x, wid = tid >> 5, lane = tid & 31;
    int g = lane >> 2, c = lane & 3;
    int z = blockIdx.z;
    int head = (MODE == 0) ? z : 0;
    const float* s1p = s1g + head * N_NODES;
    const float* Eap = Eag + head * N_NODES;
    const float* Ebp = Ebg + head * N_NODES;
    const uint4* Tp = Tg + head * NHALF;
    const uint32_t* vsrc = Vb + ((MODE == 0) ? (size_t)head * vzstride
                                             : (size_t)blockIdx.y * NCOLS * NHALF);
    int jbase = (MODE == 1) ? z * (TT * 64) : 0;
    int tbase = jbase >> 6;
    int prbase = jbase >> 1;

    int i0 = blockIdx.x * RPB;
    int rowgrp = wid % ROWG, colgrp = wid / ROWG;
    int colofs = colgrp * 64;
    int rloc = rowgrp * 16 + g;
    int r0 = i0 + rloc;

    float s1a = s1p[r0], s1b_ = s1p[r0 + 8];
    uint32_t thA2 = packbf(-s1a, -s1a), thB2 = packbf(-s1b_, -s1b_);
    uint32_t EaA2 = packbf(Eap[r0], Eap[r0]);
    uint32_t EbA2 = packbf(Ebp[r0], Ebp[r0]);
    uint32_t EaB2 = packbf(Eap[r0 + 8], Eap[r0 + 8]);
    uint32_t EbB2 = packbf(Ebp[r0 + 8], Ebp[r0 + 8]);

    float acc[8][4];
#pragma unroll
    for (int f = 0; f < 8; f++)
#pragma unroll
        for (int q = 0; q < 4; q++) acc[f][q] = 0.f;
    float accd[4] = {0.f, 0.f, 0.f, 0.f};
    uint32_t aPn[4][4];
    uint32_t vbase = smem_u32(vsm);
    // ldmatrix per-lane base: row = lane&7, matrix chunk = (lane>>3)*16B
    uint32_t a0 = vbase + (uint32_t)((lane & 7) * SVR * 4 + ((lane >> 3) << 4))
                + (uint32_t)(colofs * SVR * 4);
    uint32_t bden = (g == 0) ? 0x3F803F80u : 0u;   // bf16 {1,1} on n==0

    auto issueV = [&](int tl) {
        int buf = tl % 3;
        uint32_t bb = vbase + (uint32_t)(buf * BUF_U32) * 4;
        int pr0 = prbase + tl * 32;
        int tabs = tbase + tl;
#pragma unroll
        for (int u = 0; u < NCOLS / 32; u++) {
            int idx = tid + 256 * u;
            int d = idx >> 3, q = idx & 7;
            CP_ASYNC16(bb + (uint32_t)(d * SVR + q * 4) * 4,
                       vsrc + (size_t)d * NHALF + pr0 + q * 4);
        }
        if (tid < RPB / 2) {
            CP_ASYNC16(bb + (uint32_t)ADJ_OFF * 4 + tid * 16,
                       adjT + (size_t)tabs * N_NODES + i0 + 2 * tid);
        } else if (tid < RPB / 2 + 32) {
            int q = tid - RPB / 2;
            CP_ASYNC16(bb + (uint32_t)T_OFF * 4 + q * 16, Tp + pr0 + q);
        }
    };

    auto computeP = [&](int tl) {
        int buf = tl % 3;
        const uint32_t* bb = vsm + buf * BUF_U32;
        const uint2* adjsm = (const uint2*)(bb + ADJ_OFF);
        const uint4* Tsm = (const uint4*)(bb + T_OFF);
        uint2 w0 = adjsm[rloc];
        uint2 w1 = adjsm[rloc + 8];
        unsigned long long bm0 = (unsigned long long)w0.x | ((unsigned long long)w0.y << 32);
        unsigned long long bm1 = (unsigned long long)w1.x | ((unsigned long long)w1.y << 32);
        uint32_t l0 = (uint32_t)(bm0 >> (2 * c)), h0 = ((uint32_t)(bm0 >> 32)) >> (2 * c);
        uint32_t l1 = (uint32_t)(bm1 >> (2 * c)), h1 = ((uint32_t)(bm1 >> 32)) >> (2 * c);
#pragma unroll
        for (int ks = 0; ks < 4; ks++) {
            uint32_t wA = (ks < 2) ? l0 : h0;
            uint32_t wB = (ks < 2) ? l1 : h1;
            const int sh = (ks & 1) * 16;
            int jp0 = 8 * ks + c, jp1 = jp0 + 4;
            uint4 t0 = Tsm[jp0];
            uint4 t1 = Tsm[jp1];
            uint32_t xA = wA >> sh, xB = wB >> sh;
            uint32_t aA0 = amask2(xA),      aB0 = amask2(xB);
            uint32_t aA1 = amask2(xA >> 8), aB1 = amask2(xB >> 8);
            uint32_t mA0 = bge(t0.z, thA2), mB0 = bge(t0.z, thB2);
            uint32_t mA1 = bge(t1.z, thA2), mB1 = bge(t1.z, thB2);
            uint32_t FaA0 = bmul2(EaA2, t0.x), FbA0 = bmul2(EbA2, t0.y);
            uint32_t FaB0 = bmul2(EaB2, t0.x), FbB0 = bmul2(EbB2, t0.y);
            uint32_t FaA1 = bmul2(EaA2, t1.x), FbA1 = bmul2(EbA2, t1.y);
            uint32_t FaB1 = bmul2(EaB2, t1.x), FbB1 = bmul2(EbB2, t1.y);
            aPn[ks][0] = ((FaA0 & mA0) | (FbA0 & ~mA0)) & aA0;
            aPn[ks][1] = ((FaB0 & mB0) | (FbB0 & ~mB0)) & aB0;
            aPn[ks][2] = ((FaA1 & mA1) | (FbA1 & ~mA1)) & aA1;
            aPn[ks][3] = ((FaB1 & mB1) | (FbB1 & ~mB1)) & aB1;
        }
    };

    issueV(0); CP_COMMIT();
    issueV(1); CP_COMMIT();
    CP_WAIT(1);
    __syncthreads();
    computeP(0);

    for (int t = 0; t < TT; t++) {
        if (t + 2 < TT) { issueV(t + 2); CP_COMMIT(); }
        uint32_t ab = a0 + (uint32_t)((t % 3) * BUF_U32) * 4;
#pragma unroll
        for (int f = 0; f < 8; f++) {
            uint32_t b[8];
            LDMX4(b[0], b[1], b[2], b[3], ab + f * (8 * SVR * 4));
            LDMX4(b[4], b[5], b[6], b[7], ab + f * (8 * SVR * 4) + 64);
            mma_bf16(acc[f], aPn[0], b[0], b[1]);
            mma_bf16(acc[f], aPn[1], b[2], b[3]);
            mma_bf16(acc[f], aPn[2], b[4], b[5]);
            mma_bf16(acc[f], aPn[3], b[6], b[7]);
        }
        if (colgrp == 0) {
            mma_bf16(accd, aPn[0], bden, bden);
            mma_bf16(accd, aPn[1], bden, bden);
            mma_bf16(accd, aPn[2], bden, bden);
            mma_bf16(accd, aPn[3], bden, bden);
        }
        if (t + 1 < TT) {
            if (t + 2 < TT) CP_WAIT(1); else CP_WAIT(0);
            __syncthreads();
            computeP(t + 1);
        }
    }

    if (MODE == 0) {
        float den0 = __shfl_sync(~0u, accd[0], g << 2);
        float den1 = __shfl_sync(~0u, accd[2], g << 2);
        float dinv0 = 1.0f / den0, dinv1 = 1.0f / den1;
        float* row0 = outp + (size_t)r0 * (HEADS * HID) + head * 64 + colofs;
        float* row1 = row0 + 8 * (HEADS * HID);
#pragma unroll
        for (int f = 0; f < 8; f++) {
            int col = 8 * f + 2 * c;
            float2 v0, v1;
            v0.x = elu1(acc[f][0] * dinv0); v0.y = elu1(acc[f][1] * dinv0);
            v1.x = elu1(acc[f][2] * dinv1); v1.y = elu1(acc[f][3] * dinv1);
            *(float2*)&row0[col] = v0;
            *(float2*)&row1[col] = v1;
        }
    } else {
        float* num = outp + (size_t)z * (N_NODES * FOUT);
        int outc = blockIdx.y * NCOLS + colofs;
        float* row0 = num + (size_t)r0 * FOUT + outc;
        float* row1 = row0 + 8 * FOUT;
#pragma unroll
        for (int f = 0; f < 8; f++) {
            int col = 8 * f + 2 * c;
            float2 v0, v1;
            v0.x = acc[f][0]; v0.y = acc[f][1];
            v1.x = acc[f][2]; v1.y = acc[f][3];
            *(float2*)&row0[col] = v0;
            *(float2*)&row1[col] = v1;
        }
        if (c == 0 && colgrp == 0 && blockIdx.y == 0) {
            denp[z * N_NODES + r0] = accd[0];
            denp[z * N_NODES + r0 + 8] = accd[2];
        }
    }
}

// ---------------- combine 2 partials + elu + log_softmax ----------------
__global__ __launch_bounds__(256) void final_kernel(
    const float* __restrict__ num, const float* __restrict__ den,
    float* __restrict__ out)
{
    int warp = threadIdx.x >> 5, lane = threadIdx.x & 31;
    int row = blockIdx.x * 8 + warp;
    const float* n0 = num + (size_t)row * FOUT;
    const float* n1 = n0 + (size_t)N_NODES * FOUT;
    float dinv = 1.0f / (den[row] + den[N_NODES + row]);
    float v[8];
    float mx = -1e30f;
#pragma unroll
    for (int k = 0; k < 8; k++) {
        int idx = lane + k * 32;
        float x = (n0[idx] + n1[idx]) * dinv;
        x = elu1(x);
        v[k] = x;
        mx = fmaxf(mx, x);
    }
#pragma unroll
    for (int o = 16; o > 0; o >>= 1) mx = fmaxf(mx, __shfl_xor_sync(~0u, mx, o));
    float s = 0.f;
#pragma unroll
    for (int k = 0; k < 8; k++) s += fast_exp(v[k] - mx);
#pragma unroll
    for (int o = 16; o > 0; o >>= 1) s += __shfl_xor_sync(~0u, s, o);
    float lse = mx + logf(s);
#pragma unroll
    for (int k = 0; k < 8; k++) out[(size_t)row * FOUT + lane + k * 32] = v[k] - lse;
}

// ---------------- launcher ----------------
extern "C" void kernel_launch(void* const* d_in, const int* in_sizes, int n_in,
                              void* d_out, int out_size)
{
    const float* x        = (const float*)d_in[0];
    const int*   adj      = (const int*)  d_in[1];
    const float* W_heads  = (const float*)d_in[2];
    const float* a1_heads = (const float*)d_in[3];
    const float* a2_heads = (const float*)d_in[4];
    const float* W_out    = (const float*)d_in[5];
    const float* a1_out   = (const float*)d_in[6];
    const float* a2_out   = (const float*)d_in[7];
    float* out = (float*)d_out;

    float *hbuf, *num, *den, *s1, *s2, *s1b, *s2b, *Ea1, *Eb1, *Ea2, *Eb2;
    uint32_t *Vb1, *Vb2;
    uint4 *T1, *T2;
    uint2 *adjT;
    unsigned *enc1;
    cudaGetSymbolAddress((void**)&Vb1,  g_Vb1);
    cudaGetSymbolAddress((void**)&hbuf, g_h);
    cudaGetSymbolAddress((void**)&Vb2,  g_Vb2);
    cudaGetSymbolAddress((void**)&num,  g_num);
    cudaGetSymbolAddress((void**)&den,  g_den);
    cudaGetSymbolAddress((void**)&adjT, g_adjT);
    cudaGetSymbolAddress((void**)&s1,   g_s1);
    cudaGetSymbolAddress((void**)&s2,   g_s2);
    cudaGetSymbolAddress((void**)&s1b,  g_s1b);
    cudaGetSymbolAddress((void**)&s2b,  g_s2b);
    cudaGetSymbolAddress((void**)&enc1, g_enc1);
    cudaGetSymbolAddress((void**)&Ea1,  g_Ea1);
    cudaGetSymbolAddress((void**)&Eb1,  g_Eb1);
    cudaGetSymbolAddress((void**)&T1,   g_T1);
    cudaGetSymbolAddress((void**)&Ea2,  g_Ea2);
    cudaGetSymbolAddress((void**)&Eb2,  g_Eb2);
    cudaGetSymbolAddress((void**)&T2,   g_T2);

    const int SM1 = (64 * 36 + 256 + 128) * 4 * 3;     // 32256 B
    const int SM2 = (128 * 36 + 128 + 128) * 4 * 3;    // 58368 B
    cudaFuncSetAttribute(attn_mma<HID, 128, 64, 0>,
                         cudaFuncAttributeMaxDynamicSharedMemorySize, SM1);
    cudaFuncSetAttribute(attn_mma<128, 64, 32, 1>,
                         cudaFuncAttributeMaxDynamicSharedMemorySize, SM2);

    // 0: adj transposed bitmask + zeroing
    pack_adj<<<(N_NODES * 64) / 256, 256>>>(adj, adjT, s1b, s2b, enc1);
    // 1: layer-1 GEMM (+V d-major bf16 pairs, s1/s2, s2max)
    gemm_tc<1><<<dim3(N_NODES / 128, 1, HEADS), 256>>>(
        x, W_heads, Vb1, a1_heads, a2_heads, s1, s2, enc1,
        HID, FIN * HID, HID * NHALF, HID, N_NODES);
    // 2: layer-1 row factors + pair tables
    prep1<<<(HEADS * N_NODES) / 256, 256>>>(s1, s2, enc1, Ea1, Eb1, T1);
    // 3: layer-1 attention (<- profiled slot)
    attn_mma<HID, 128, 64, 0><<<dim3(N_NODES / 128, 1, HEADS), 256, SM1>>>(
        Vb1, HID * NHALF, s1, Ea1, Eb1, T1, adjT, hbuf, nullptr);
    // 4: layer-2 GEMM
    gemm_tc<0><<<dim3(N_NODES / 128, FOUT / 64, 1), 256>>>(
        hbuf, W_out, Vb2, a1_out, a2_out, s1b, s2b, enc1, FOUT, 0, 0, 0, 0);
    // 5: layer-2 max + tables
    max2_prep2<<<1, 256>>>(s1b, s2b, Ea2, Eb2, T2);
    // 6: layer-2 attention (j-split x2 partials)
    attn_mma<128, 64, 32, 1><<<dim3(N_NODES / 64, 2, 2), 256, SM2>>>(
        Vb2, 0, s1b, Ea2, Eb2, T2, adjT, num, den);
    // 7: combine + elu + log_softmax
    final_kernel<<<N_NODES / 8, 256>>>(num, den, out);
}